// round 7
// baseline (speedup 1.0000x reference)
#include <cuda_runtime.h>

// LSTM2LINEAR: B=8192, T=1024, H=10, scalar input.
// f32x2 lanes carry TWO BATCHES (weights are batch-invariant):
//   lane = (batch-pair, r); accumulator per gate = {gate^b0, gate^b1}.
// One warp per block: 3 batch-pairs x 10 lanes = 6 batches / warp (lanes 30,31 dummy).
// h exchanged as {2h^b0, 2h^b1} ull pairs in a tiny double-buffered shared array
// (one __syncwarp per step). Nonlinearities: tanh.approx.f32 (5 MUFU/elem-step);
// sigma(x)=0.5*tanh(x/2)+0.5 with the 0.5 arg-scale folded into weights.
// h is stored DOUBLED (2h = fma(to,tc,tc)) with an extra 0.5 folded into W_hh,
// saving a multiply per step. Each gate's dot product is split into two
// independent 5/6-length chains (+add.rn.f32x2) to shorten the critical path.

#define T_STEPS 1024
#define HDIM 10

typedef unsigned long long ull;

__device__ __forceinline__ ull pk(float lo, float hi) {
    ull v;
    asm("mov.b64 %0, {%1, %2};" : "=l"(v)
        : "r"(__float_as_uint(lo)), "r"(__float_as_uint(hi)));
    return v;
}
__device__ __forceinline__ float2 upk(ull v) {
    unsigned int lo, hi;
    asm("mov.b64 {%0, %1}, %2;" : "=r"(lo), "=r"(hi) : "l"(v));
    return make_float2(__uint_as_float(lo), __uint_as_float(hi));
}
__device__ __forceinline__ ull fma2(ull a, ull b, ull c) {
    ull d;
    asm("fma.rn.f32x2 %0, %1, %2, %3;" : "=l"(d) : "l"(a), "l"(b), "l"(c));
    return d;
}
__device__ __forceinline__ ull mul2(ull a, ull b) {
    ull d;
    asm("mul.rn.f32x2 %0, %1, %2;" : "=l"(d) : "l"(a), "l"(b));
    return d;
}
__device__ __forceinline__ ull add2(ull a, ull b) {
    ull d;
    asm("add.rn.f32x2 %0, %1, %2;" : "=l"(d) : "l"(a), "l"(b));
    return d;
}
__device__ __forceinline__ float tanha(float x) {
    float y; asm("tanh.approx.f32 %0, %1;" : "=f"(y) : "f"(x)); return y;
}

// 12-op gate accumulation: two independent chains + combine.
#define GATE_ACC(a, w, xx, u2, b2)                              \
    {                                                            \
        ull _a = fma2(xx, u2, b2);                               \
        _a = fma2(w[0], q0.x, _a);                               \
        _a = fma2(w[1], q0.y, _a);                               \
        _a = fma2(w[2], q1.x, _a);                               \
        _a = fma2(w[3], q1.y, _a);                               \
        _a = fma2(w[4], q2.x, _a);                               \
        ull _b = mul2(w[5], q2.y);                               \
        _b = fma2(w[6], q3.x, _b);                               \
        _b = fma2(w[7], q3.y, _b);                               \
        _b = fma2(w[8], q4.x, _b);                               \
        _b = fma2(w[9], q4.y, _b);                               \
        a = add2(_a, _b);                                        \
    }

__global__ void __launch_bounds__(32)
lstm2linear_kernel(const float* __restrict__ x,      // [B, T]
                   const float* __restrict__ W_ih,   // [4H, 1]
                   const float* __restrict__ W_hh,   // [4H, H]
                   const float* __restrict__ b_ih,   // [4H]
                   const float* __restrict__ b_hh,   // [4H]
                   const float* __restrict__ W_lin,  // [1, H]
                   const float* __restrict__ b_lin,  // [1]
                   float* __restrict__ out,          // [B]
                   int B)
{
    // hs[buf][group][j] = {2*h_j^b0, 2*h_j^b1}
    __shared__ ull hs[2][4][HDIM];

    const int lane = threadIdx.x;
    const int g = lane / HDIM;              // 0..3 (3 = dummy, lanes 30/31)
    const int r = lane % HDIM;              // 0..9
    const int nPairs = B >> 1;              // 4096
    const int P = blockIdx.x * 3 + g;       // batch-pair index
    const bool active = (g < 3) && (P < nPairs);
    const int Pc = (P < nPairs) ? P : (nPairs - 1);
    const int b0 = 2 * Pc, b1 = 2 * Pc + 1;

    // Scale folding:
    //  - sigmoid half-arg (i,f,o): 0.5 on W_ih, biases, W_hh.
    //  - g gate: 1.0.
    //  - h stored doubled: extra 0.5 on ALL W_hh entries.
    const float SHH_IFO = 0.25f, SHH_G = 0.5f;
    const float SXB_IFO = 0.5f,  SXB_G = 1.0f;

    ull wI[HDIM], wF[HDIM], wG[HDIM], wO[HDIM];
#pragma unroll
    for (int j = 0; j < HDIM; j++) {
        float vi = SHH_IFO * W_hh[(0 * HDIM + r) * HDIM + j];
        float vf = SHH_IFO * W_hh[(1 * HDIM + r) * HDIM + j];
        float vg = SHH_G   * W_hh[(2 * HDIM + r) * HDIM + j];
        float vo = SHH_IFO * W_hh[(3 * HDIM + r) * HDIM + j];
        wI[j] = pk(vi, vi); wF[j] = pk(vf, vf);
        wG[j] = pk(vg, vg); wO[j] = pk(vo, vo);
    }
    float t;
    t = SXB_IFO * W_ih[0 * HDIM + r];                      const ull uI2 = pk(t, t);
    t = SXB_IFO * W_ih[1 * HDIM + r];                      const ull uF2 = pk(t, t);
    t = SXB_G   * W_ih[2 * HDIM + r];                      const ull uG2 = pk(t, t);
    t = SXB_IFO * W_ih[3 * HDIM + r];                      const ull uO2 = pk(t, t);
    t = SXB_IFO * (b_ih[0 * HDIM + r] + b_hh[0 * HDIM + r]); const ull bI2 = pk(t, t);
    t = SXB_IFO * (b_ih[1 * HDIM + r] + b_hh[1 * HDIM + r]); const ull bF2 = pk(t, t);
    t = SXB_G   * (b_ih[2 * HDIM + r] + b_hh[2 * HDIM + r]); const ull bG2 = pk(t, t);
    t = SXB_IFO * (b_ih[3 * HDIM + r] + b_hh[3 * HDIM + r]); const ull bO2 = pk(t, t);
    const float wlin = W_lin[r];
    const ull HALF2 = pk(0.5f, 0.5f);

    ull C = 0ull;   // {c^b0, c^b1}, true scale

    hs[0][g][r] = 0ull;
    hs[1][g][r] = 0ull;
    if (g == 0) { hs[0][3][r] = 0ull; hs[1][3][r] = 0ull; }
    __syncwarp();

    const float* xb0 = x + (size_t)b0 * T_STEPS;
    const float* xb1 = x + (size_t)b1 * T_STEPS;

    const ulonglong2* rdp = reinterpret_cast<const ulonglong2*>(&hs[0][g][0]);
    ull* wrp = &hs[1][g][0];

    float4 xv0 = *reinterpret_cast<const float4*>(xb0);
    float4 xv1 = *reinterpret_cast<const float4*>(xb1);

    for (int t0 = 0; t0 < T_STEPS; t0 += 4) {
        const int tn = (t0 + 4 < T_STEPS) ? (t0 + 4) : t0;
        const float4 xn0 = *reinterpret_cast<const float4*>(xb0 + tn);
        const float4 xn1 = *reinterpret_cast<const float4*>(xb1 + tn);
#pragma unroll
        for (int k = 0; k < 4; k++) {
            const float xt0 = (k == 0) ? xv0.x : (k == 1) ? xv0.y :
                              (k == 2) ? xv0.z : xv0.w;
            const float xt1 = (k == 0) ? xv1.x : (k == 1) ? xv1.y :
                              (k == 2) ? xv1.z : xv1.w;
            const ull xx = pk(xt0, xt1);

            const ulonglong2 q0 = rdp[0], q1 = rdp[1], q2 = rdp[2],
                             q3 = rdp[3], q4 = rdp[4];

            ull aI, aF, aG, aO;
            GATE_ACC(aI, wI, xx, uI2, bI2);   // {i/2}
            GATE_ACC(aF, wF, xx, uF2, bF2);   // {f/2}
            GATE_ACC(aG, wG, xx, uG2, bG2);   // {g}
            GATE_ACC(aO, wO, xx, uO2, bO2);   // {o/2}

            const float2 vI = upk(aI), vF = upk(aF),
                         vG = upk(aG), vO = upk(aO);
            const ull ti2 = pk(tanha(vI.x), tanha(vI.y));
            const ull tf2 = pk(tanha(vF.x), tanha(vF.y));
            const ull tg2 = pk(tanha(vG.x), tanha(vG.y));
            const ull to2 = pk(tanha(vO.x), tanha(vO.y));

            const ull si2 = fma2(HALF2, ti2, HALF2);   // sigmoid(i)
            const ull sf2 = fma2(HALF2, tf2, HALF2);   // sigmoid(f)
            C = fma2(sf2, C, mul2(si2, tg2));

            const float2 cv = upk(C);
            const ull tc2 = pk(tanha(cv.x), tanha(cv.y));
            const ull hn2 = fma2(to2, tc2, tc2);       // {2h^b0, 2h^b1}

            wrp[r] = hn2;
            __syncwarp();
            // swap buffers
            ull* nw = const_cast<ull*>(reinterpret_cast<const ull*>(rdp));
            rdp = reinterpret_cast<const ulonglong2*>(wrp);
            wrp = nw;
        }
        xv0 = xn0;
        xv1 = xn1;
    }

    // ---- output: out[b] = sum_r c_r * W_lin[r] + b_lin (both batches) ----
    __syncwarp();
    ull* scr = &hs[0][0][0];
    scr[g * HDIM + r] = mul2(C, pk(wlin, wlin));
    __syncwarp();
    if (active && r == 0) {
        ull s = scr[g * HDIM + 0];
#pragma unroll
        for (int j = 1; j < HDIM; j++) s = add2(s, scr[g * HDIM + j]);
        const float2 sv = upk(s);
        const float bl = b_lin[0];
        out[b0] = sv.x + bl;
        out[b1] = sv.y + bl;
    }
}

extern "C" void kernel_launch(void* const* d_in, const int* in_sizes, int n_in,
                              void* d_out, int out_size) {
    const float* x     = (const float*)d_in[0];  // [B, T, 1]
    const float* W_ih  = (const float*)d_in[1];  // [4H, 1]
    const float* W_hh  = (const float*)d_in[2];  // [4H, H]
    const float* b_ih  = (const float*)d_in[3];  // [4H]
    const float* b_hh  = (const float*)d_in[4];  // [4H]
    const float* W_lin = (const float*)d_in[5];  // [1, H]
    const float* b_lin = (const float*)d_in[6];  // [1]
    float* out = (float*)d_out;                  // [B, 1]

    const int B = in_sizes[0] / T_STEPS;         // 8192
    const int nPairs = B / 2;                    // 4096
    const int blocks = (nPairs + 2) / 3;         // 1366 single-warp blocks

    lstm2linear_kernel<<<blocks, 32>>>(x, W_ih, W_hh, b_ih, b_hh,
                                       W_lin, b_lin, out, B);
}

// round 8
// speedup vs baseline: 1.0429x; 1.0429x over previous
#include <cuda_runtime.h>

// LSTM2LINEAR: B=8192, T=1024, H=10, scalar input.
// R4 layout (best: 2731 warps): one warp per block, 3 batches x 10 lanes
// (lanes 30,31 dummy). Gate-pair f32x2 packing: (i,f) and (g,o) accumulators.
// tanh.approx for all nonlinearities (5 MUFU/elem-step), sigmoid half-arg and
// doubled-h scales folded into weights. This round: each gate's 11-deep fma2
// chain split into independent 6+5 halves + add2 (critical path 44 -> ~28 cy),
// 8-step x prefetch, index-flip double buffer.

#define T_STEPS 1024
#define HDIM 10

typedef unsigned long long ull;

__device__ __forceinline__ ull pk(float lo, float hi) {
    ull v;
    asm("mov.b64 %0, {%1, %2};" : "=l"(v)
        : "r"(__float_as_uint(lo)), "r"(__float_as_uint(hi)));
    return v;
}
__device__ __forceinline__ float2 upk(ull v) {
    unsigned int lo, hi;
    asm("mov.b64 {%0, %1}, %2;" : "=r"(lo), "=r"(hi) : "l"(v));
    return make_float2(__uint_as_float(lo), __uint_as_float(hi));
}
__device__ __forceinline__ ull fma2(ull a, ull b, ull c) {
    ull d;
    asm("fma.rn.f32x2 %0, %1, %2, %3;" : "=l"(d) : "l"(a), "l"(b), "l"(c));
    return d;
}
__device__ __forceinline__ ull mul2(ull a, ull b) {
    ull d;
    asm("mul.rn.f32x2 %0, %1, %2;" : "=l"(d) : "l"(a), "l"(b));
    return d;
}
__device__ __forceinline__ ull add2(ull a, ull b) {
    ull d;
    asm("add.rn.f32x2 %0, %1, %2;" : "=l"(d) : "l"(a), "l"(b));
    return d;
}
__device__ __forceinline__ float tanha(float x) {
    float y; asm("tanh.approx.f32 %0, %1;" : "=f"(y) : "f"(x)); return y;
}

// Gate accumulation, two independent chains (depth 6 and 5) + combine.
#define GATE_ACC(a, w, xx, u2, b2)                              \
    {                                                            \
        ull _ca = fma2(xx, u2, b2);                              \
        _ca = fma2(w[0], q0.x, _ca);                             \
        _ca = fma2(w[1], q0.y, _ca);                             \
        _ca = fma2(w[2], q1.x, _ca);                             \
        _ca = fma2(w[3], q1.y, _ca);                             \
        _ca = fma2(w[4], q2.x, _ca);                             \
        ull _cb = mul2(w[5], q2.y);                              \
        _cb = fma2(w[6], q3.x, _cb);                             \
        _cb = fma2(w[7], q3.y, _cb);                             \
        _cb = fma2(w[8], q4.x, _cb);                             \
        _cb = fma2(w[9], q4.y, _cb);                             \
        a = add2(_ca, _cb);                                      \
    }

__global__ void __launch_bounds__(32)
lstm2linear_kernel(const float* __restrict__ x,      // [B, T]
                   const float* __restrict__ W_ih,   // [4H, 1]
                   const float* __restrict__ W_hh,   // [4H, H]
                   const float* __restrict__ b_ih,   // [4H]
                   const float* __restrict__ b_hh,   // [4H]
                   const float* __restrict__ W_lin,  // [1, H]
                   const float* __restrict__ b_lin,  // [1]
                   float* __restrict__ out,          // [B]
                   int B)
{
    // hs[buf][group][j] = {2h_j, 2h_j} (h stored doubled; 0.5 folded into W_hh)
    __shared__ ull hs[2][4][HDIM];

    const int lane = threadIdx.x;
    const int g = lane / HDIM;          // 0..3 (3 = dummy group, lanes 30/31)
    const int r = lane % HDIM;          // 0..9
    const int b = blockIdx.x * 3 + g;
    const bool active = (g < 3) && (b < B);
    const int bc = (b < B) ? b : (B - 1);

    // Scale folding:
    //   sigmoid half-arg (i,f,o): x0.5 on W_ih/bias/W_hh rows.
    //   h stored doubled (2h):    extra x0.5 on all W_hh entries.
    const float SHH_IFO = 0.25f, SHH_G = 0.5f;
    const float SXB_IFO = 0.5f,  SXB_G = 1.0f;

    ull wIF[HDIM], wGO[HDIM];
#pragma unroll
    for (int j = 0; j < HDIM; j++) {
        wIF[j] = pk(SHH_IFO * W_hh[(0 * HDIM + r) * HDIM + j],
                    SHH_IFO * W_hh[(1 * HDIM + r) * HDIM + j]);
        wGO[j] = pk(SHH_G   * W_hh[(2 * HDIM + r) * HDIM + j],
                    SHH_IFO * W_hh[(3 * HDIM + r) * HDIM + j]);
    }
    const ull uIF = pk(SXB_IFO * W_ih[0 * HDIM + r], SXB_IFO * W_ih[1 * HDIM + r]);
    const ull uGO = pk(SXB_G   * W_ih[2 * HDIM + r], SXB_IFO * W_ih[3 * HDIM + r]);
    const ull bIF = pk(SXB_IFO * (b_ih[0 * HDIM + r] + b_hh[0 * HDIM + r]),
                       SXB_IFO * (b_ih[1 * HDIM + r] + b_hh[1 * HDIM + r]));
    const ull bGO = pk(SXB_G   * (b_ih[2 * HDIM + r] + b_hh[2 * HDIM + r]),
                       SXB_IFO * (b_ih[3 * HDIM + r] + b_hh[3 * HDIM + r]));
    const float wlin = W_lin[r];

    float c = 0.0f;

    hs[0][g][r] = 0ull;
    hs[1][g][r] = 0ull;
    if (g == 0) { hs[0][3][r] = 0ull; hs[1][3][r] = 0ull; }
    __syncwarp();

    const float* xb = x + (size_t)bc * T_STEPS;
    int p = 0;

    // 8-step pipeline: hold two float4's of x, prefetch the next two.
    float4 xv0 = *reinterpret_cast<const float4*>(xb);
    float4 xv1 = *reinterpret_cast<const float4*>(xb + 4);

    for (int t0 = 0; t0 < T_STEPS; t0 += 8) {
        const int tn = (t0 + 8 < T_STEPS) ? (t0 + 8) : t0;
        const float4 xn0 = *reinterpret_cast<const float4*>(xb + tn);
        const float4 xn1 = *reinterpret_cast<const float4*>(xb + tn + 4);
#pragma unroll
        for (int k = 0; k < 8; k++) {
            const float4& xq = (k < 4) ? xv0 : xv1;
            const int kk = k & 3;
            const float xt = (kk == 0) ? xq.x : (kk == 1) ? xq.y :
                             (kk == 2) ? xq.z : xq.w;
            const ull xx = pk(xt, xt);

            const ulonglong2* hp =
                reinterpret_cast<const ulonglong2*>(&hs[p][g][0]);
            const ulonglong2 q0 = hp[0], q1 = hp[1], q2 = hp[2],
                             q3 = hp[3], q4 = hp[4];

            ull aIF, aGO;
            GATE_ACC(aIF, wIF, xx, uIF, bIF);   // {i/2, f/2}
            GATE_ACC(aGO, wGO, xx, uGO, bGO);   // {g,   o/2}

            const float2 gif = upk(aIF);
            const float2 ggo = upk(aGO);
            const float ti = tanha(gif.x);
            const float tf = tanha(gif.y);
            const float tg = tanha(ggo.x);
            const float to = tanha(ggo.y);

            const float si = fmaf(0.5f, ti, 0.5f);   // sigmoid(i)
            const float sf = fmaf(0.5f, tf, 0.5f);   // sigmoid(f)
            c = fmaf(sf, c, si * tg);

            const float tc = tanha(c);
            const float hn2 = fmaf(to, tc, tc);      // 2h = (to+1)*tc

            hs[p ^ 1][g][r] = pk(hn2, hn2);
            __syncwarp();
            p ^= 1;
        }
        xv0 = xn0;
        xv1 = xn1;
    }

    // ---- output: out[b] = sum_r c_r * W_lin[r] + b_lin ----
    __syncwarp();
    float* scr = reinterpret_cast<float*>(hs);
    scr[g * HDIM + r] = c * wlin;
    __syncwarp();
    if (active && r == 0) {
        float s = b_lin[0];
#pragma unroll
        for (int j = 0; j < HDIM; j++) s += scr[g * HDIM + j];
        out[b] = s;
    }
}

extern "C" void kernel_launch(void* const* d_in, const int* in_sizes, int n_in,
                              void* d_out, int out_size) {
    const float* x     = (const float*)d_in[0];  // [B, T, 1]
    const float* W_ih  = (const float*)d_in[1];  // [4H, 1]
    const float* W_hh  = (const float*)d_in[2];  // [4H, H]
    const float* b_ih  = (const float*)d_in[3];  // [4H]
    const float* b_hh  = (const float*)d_in[4];  // [4H]
    const float* W_lin = (const float*)d_in[5];  // [1, H]
    const float* b_lin = (const float*)d_in[6];  // [1]
    float* out = (float*)d_out;                  // [B, 1]

    const int B = in_sizes[0] / T_STEPS;         // 8192
    const int blocks = (B + 2) / 3;              // 2731 single-warp blocks

    lstm2linear_kernel<<<blocks, 32>>>(x, W_ih, W_hh, b_ih, b_hh,
                                       W_lin, b_lin, out, B);
}